// round 5
// baseline (speedup 1.0000x reference)
#include <cuda_runtime.h>
#include <cuda_bf16.h>
#include <math.h>
#include <stdint.h>

#define S    2048
#define NH   32
#define HD   128
#define HID  4096
#define KEEP 206
#define TOPK 204
#define MV   -1000000000.0f
#define RSQ  0.08838834764831845f   /* 1/sqrt(128) */

typedef __nv_bfloat16 bf16;

// ---------------- device scratch ----------------
static __device__ float g_Q[NH * S * HD];
static __device__ float g_K[NH * S * HD];
static __device__ float g_V[NH * S * HD];
static __device__ float g_AW[NH * S * S];           // masked logits (lower tri valid)
static __device__ float g_rowm[NH * S];
static __device__ float g_rowz[NH * S];
static __device__ float g_scores[NH * S];
static __device__ int   g_kidx[NH * KEEP];
static __device__ float g_negc[NH * HD];
static __device__ float g_cos[S * 64];
static __device__ float g_sin[S * 64];

// bf16 hi/lo split operand arrays
static __device__ bf16 g_Hh[S * HID],  g_Hl[S * HID];
static __device__ bf16 g_Wh[3 * HID * HID], g_Wl[3 * HID * HID];   // Wq|Wk|Wv
static __device__ bf16 g_Woh[HID * HID], g_Wol[HID * HID];
static __device__ bf16 g_Qh[NH * S * HD], g_Ql[NH * S * HD];       // post-rope
static __device__ bf16 g_Kh[NH * S * HD], g_Kl[NH * S * HD];
static __device__ bf16 g_Kkh[NH * 256 * HD], g_Kkl[NH * 256 * HD];
static __device__ bf16 g_VkTh[NH * HD * 256], g_VkTl[NH * HD * 256];
static __device__ bf16 g_awkh[NH * S * 256], g_awkl[NH * S * 256];
static __device__ bf16 g_oph[S * HID], g_opl[S * HID];

// ---------------- helpers ----------------
__device__ __forceinline__ void split1(float v, bf16& h, bf16& l) {
    h = __float2bfloat16(v);
    l = __float2bfloat16(v - __bfloat162float(h));
}

// which: 0=hidden, 1=Wq, 2=Wk, 3=Wv, 4=Wo  (destination resolved on device)
__global__ void split_into_kernel(const float* __restrict__ X, int which, int n4) {
    int i = blockIdx.x * 256 + threadIdx.x;
    if (i >= n4) return;
    bf16 *Xh, *Xl;
    if (which == 0)      { Xh = g_Hh;  Xl = g_Hl; }
    else if (which <= 3) { size_t o = (size_t)(which - 1) * HID * HID;
                           Xh = g_Wh + o; Xl = g_Wl + o; }
    else                 { Xh = g_Woh; Xl = g_Wol; }
    float4 v = ((const float4*)X)[i];
    bf16 h0, l0, h1, l1, h2, l2, h3, l3;
    split1(v.x, h0, l0); split1(v.y, h1, l1);
    split1(v.z, h2, l2); split1(v.w, h3, l3);
    ((__nv_bfloat162*)Xh)[2 * i]     = __nv_bfloat162(h0, h1);
    ((__nv_bfloat162*)Xh)[2 * i + 1] = __nv_bfloat162(h2, h3);
    ((__nv_bfloat162*)Xl)[2 * i]     = __nv_bfloat162(l0, l1);
    ((__nv_bfloat162*)Xl)[2 * i + 1] = __nv_bfloat162(l2, l3);
}

// ---------------- RoPE ----------------
__global__ void rope_table_kernel() {
    int idx = blockIdx.x * blockDim.x + threadIdx.x;
    if (idx >= S * 64) return;
    int s = idx >> 6, i = idx & 63;
    double inv = exp(-((double)i / 64.0) * log(10000.0));
    float ph = (float)s * (float)inv;
    g_cos[idx] = cosf(ph);
    g_sin[idx] = sinf(ph);
}

__global__ void rope_apply_kernel() {
    int idx = blockIdx.x * blockDim.x + threadIdx.x;
    if (idx >= NH * S * 64) return;
    int i = idx & 63;
    int s = (idx >> 6) & (S - 1);
    int h = idx >> 17;
    float c  = g_cos[(s << 6) + i];
    float sn = g_sin[(s << 6) + i];
    size_t base = ((size_t)h * S + s) * HD;
    float a = g_Q[base + i], b = g_Q[base + i + 64];
    split1(a * c - b * sn, g_Qh[base + i],      g_Ql[base + i]);
    split1(b * c + a * sn, g_Qh[base + i + 64], g_Ql[base + i + 64]);
    a = g_K[base + i]; b = g_K[base + i + 64];
    split1(a * c - b * sn, g_Kh[base + i],      g_Kl[base + i]);
    split1(b * c + a * sn, g_Kh[base + i + 64], g_Kl[base + i + 64]);
}

// ---------------- tensor-core pipelined NT GEMM ----------------
enum { M_PROJ = 0, M_LOGITS = 1, M_SP1 = 2, M_SP2 = 3, M_FINAL = 4 };

__device__ __forceinline__ void ldsm4(uint32_t* r, const void* p) {
    uint32_t addr = (uint32_t)__cvta_generic_to_shared(p);
    asm volatile("ldmatrix.sync.aligned.m8n8.x4.shared.b16 {%0,%1,%2,%3},[%4];\n"
                 : "=r"(r[0]), "=r"(r[1]), "=r"(r[2]), "=r"(r[3]) : "r"(addr));
}
__device__ __forceinline__ void mma16816(float* c, const uint32_t* a, const uint32_t* b) {
    asm volatile("mma.sync.aligned.m16n8k16.row.col.f32.bf16.bf16.f32 "
                 "{%0,%1,%2,%3},{%4,%5,%6,%7},{%8,%9},{%0,%1,%2,%3};\n"
                 : "+f"(c[0]), "+f"(c[1]), "+f"(c[2]), "+f"(c[3])
                 : "r"(a[0]), "r"(a[1]), "r"(a[2]), "r"(a[3]), "r"(b[0]), "r"(b[1]));
}
__device__ __forceinline__ void cpa16(void* smem, const void* gmem) {
    uint32_t s = (uint32_t)__cvta_generic_to_shared(smem);
    asm volatile("cp.async.ca.shared.global [%0],[%1],16;\n" :: "r"(s), "l"(gmem));
}

#define LDA 40                  // bf16/row (80B stride)
#define ARR_B (128 * LDA * 2)   // 10240B per array
#define STG_B (4 * ARR_B)       // 40960B per stage

template <int MODE>
__global__ void __launch_bounds__(256, 2)
gemm_tc2(float* __restrict__ Cg, int K)
{
    if (MODE == M_LOGITS && blockIdx.x > blockIdx.y) return;

    const int h = blockIdx.z;
    const bf16 *Ah, *Al, *Bh, *Bl;
    if (MODE == M_PROJ)        { Ah = g_Hh;  Al = g_Hl;  Bh = g_Wh;  Bl = g_Wl; }
    else if (MODE == M_LOGITS) { Ah = g_Qh + (size_t)h * S * HD;  Al = g_Ql + (size_t)h * S * HD;
                                 Bh = g_Kh + (size_t)h * S * HD;  Bl = g_Kl + (size_t)h * S * HD; }
    else if (MODE == M_SP1)    { Ah = g_Qh + (size_t)h * S * HD;  Al = g_Ql + (size_t)h * S * HD;
                                 Bh = g_Kkh + (size_t)h * 256 * HD; Bl = g_Kkl + (size_t)h * 256 * HD; }
    else if (MODE == M_SP2)    { Ah = g_awkh + (size_t)h * S * 256; Al = g_awkl + (size_t)h * S * 256;
                                 Bh = g_VkTh + (size_t)h * HD * 256; Bl = g_VkTl + (size_t)h * HD * 256; }
    else                       { Ah = g_oph; Al = g_opl; Bh = g_Woh; Bl = g_Wol; }

    extern __shared__ char sm[];
    const int bx = blockIdx.x * 128, by = blockIdx.y * 128;
    const int tid = threadIdx.x, lane = tid & 31, w = tid >> 5;
    const int wm = (w & 1) * 64, wn = (w >> 1) * 32;

    const int lrow = tid >> 1;
    const int cbyte = (tid & 1) * 32;
    const int celem = cbyte >> 1;
    const size_t gA = (size_t)(by + lrow) * K + celem;
    const size_t gB = (size_t)(bx + lrow) * K + celem;
    const int sOff = lrow * (LDA * 2) + cbyte;

    float acc[4][4][4];
#pragma unroll
    for (int i = 0; i < 4; i++)
#pragma unroll
        for (int j = 0; j < 4; j++)
#pragma unroll
            for (int e = 0; e < 4; e++) acc[i][j][e] = 0.f;

    const int nk = K >> 5;

    {   // prologue: stage 0
        char* st = sm;
        cpa16(st + 0 * ARR_B + sOff,      Ah + gA);
        cpa16(st + 0 * ARR_B + sOff + 16, Ah + gA + 8);
        cpa16(st + 1 * ARR_B + sOff,      Al + gA);
        cpa16(st + 1 * ARR_B + sOff + 16, Al + gA + 8);
        cpa16(st + 2 * ARR_B + sOff,      Bh + gB);
        cpa16(st + 2 * ARR_B + sOff + 16, Bh + gB + 8);
        cpa16(st + 3 * ARR_B + sOff,      Bl + gB);
        cpa16(st + 3 * ARR_B + sOff + 16, Bl + gB + 8);
        asm volatile("cp.async.commit_group;\n");
    }

    for (int c = 0; c < nk; c++) {
        const int cur = c & 1;
        if (c + 1 < nk) {
            char* st = sm + (cur ^ 1) * STG_B;
            const size_t k1 = (size_t)(c + 1) * 32;
            cpa16(st + 0 * ARR_B + sOff,      Ah + gA + k1);
            cpa16(st + 0 * ARR_B + sOff + 16, Ah + gA + k1 + 8);
            cpa16(st + 1 * ARR_B + sOff,      Al + gA + k1);
            cpa16(st + 1 * ARR_B + sOff + 16, Al + gA + k1 + 8);
            cpa16(st + 2 * ARR_B + sOff,      Bh + gB + k1);
            cpa16(st + 2 * ARR_B + sOff + 16, Bh + gB + k1 + 8);
            cpa16(st + 3 * ARR_B + sOff,      Bl + gB + k1);
            cpa16(st + 3 * ARR_B + sOff + 16, Bl + gB + k1 + 8);
            asm volatile("cp.async.commit_group;\n");
            asm volatile("cp.async.wait_group 1;\n");
        } else {
            asm volatile("cp.async.wait_group 0;\n");
        }
        __syncthreads();

        const bf16* sAh = (const bf16*)(sm + cur * STG_B + 0 * ARR_B);
        const bf16* sAl = (const bf16*)(sm + cur * STG_B + 1 * ARR_B);
        const bf16* sBh = (const bf16*)(sm + cur * STG_B + 2 * ARR_B);
        const bf16* sBl = (const bf16*)(sm + cur * STG_B + 3 * ARR_B);

#pragma unroll
        for (int kc = 0; kc < 32; kc += 16) {
            // term-resequenced: peak live fragments = a1(16)+a2(16)+b(8)
            uint32_t a1[4][4], a2[4][4], b[4][2];
            const int ar = (lane & 15), ac = kc + (lane >> 4) * 8;
            const int br = (lane & 7) + ((lane >> 4) & 1) * 8, bc = kc + ((lane >> 3) & 1) * 8;
#pragma unroll
            for (int mi = 0; mi < 4; mi++) ldsm4(a1[mi], sAh + (wm + mi * 16 + ar) * LDA + ac);
#pragma unroll
            for (int pi = 0; pi < 2; pi++) ldsm4(&b[2 * pi][0], sBh + (wn + pi * 16 + br) * LDA + bc);
#pragma unroll
            for (int mi = 0; mi < 4; mi++)
#pragma unroll
                for (int ni = 0; ni < 4; ni++) mma16816(acc[mi][ni], a1[mi], b[ni]);   // hh
#pragma unroll
            for (int mi = 0; mi < 4; mi++) ldsm4(a2[mi], sAl + (wm + mi * 16 + ar) * LDA + ac);
#pragma unroll
            for (int mi = 0; mi < 4; mi++)
#pragma unroll
                for (int ni = 0; ni < 4; ni++) mma16816(acc[mi][ni], a2[mi], b[ni]);   // lh
#pragma unroll
            for (int pi = 0; pi < 2; pi++) ldsm4(&b[2 * pi][0], sBl + (wn + pi * 16 + br) * LDA + bc);
#pragma unroll
            for (int mi = 0; mi < 4; mi++)
#pragma unroll
                for (int ni = 0; ni < 4; ni++) mma16816(acc[mi][ni], a1[mi], b[ni]);   // hl
        }
        __syncthreads();
    }

    // ---------------- epilogue ----------------
#pragma unroll
    for (int mi = 0; mi < 4; mi++)
#pragma unroll
        for (int ni = 0; ni < 4; ni++)
#pragma unroll
            for (int e = 0; e < 4; e++) {
                const int row = by + wm + mi * 16 + (lane >> 2) + (e >> 1) * 8;
                const int col = bx + wn + ni * 8 + (lane & 3) * 2 + (e & 1);
                float v = acc[mi][ni][e];
                if (MODE == M_PROJ) {
                    const int which = col >> 12, inner = col & 4095;
                    float* D = (which == 0) ? g_Q : (which == 1) ? g_K : g_V;
                    D[((size_t)(inner >> 7) * S + row) * HD + (inner & 127)] = v;
                } else if (MODE == M_LOGITS) {
                    v *= RSQ;
                    if (col > row) v = fmaxf(v + MV, MV);
                    g_AW[((size_t)h * S + row) * S + col] = v;
                } else if (MODE == M_SP1) {
                    if (col < KEEP) {
                        v *= RSQ;
                        int kk = g_kidx[h * KEEP + col];
                        if (kk > row) v = fmaxf(v + MV, MV);
                    } else v = 0.f;
                    size_t o = ((size_t)h * S + row) * 256 + col;
                    split1(v, g_awkh[o], g_awkl[o]);
                } else if (MODE == M_SP2) {
                    v += g_negc[h * HD + col];
                    size_t o = (size_t)row * HID + h * HD + col;
                    split1(v, g_oph[o], g_opl[o]);
                } else {
                    Cg[(size_t)row * HID + col] = v;
                }
            }
}

// ---------------- softmax stats ----------------
__global__ void rowstats_kernel() {
    const int h = blockIdx.y;
    const int q = blockIdx.x * 8 + (threadIdx.x >> 5);
    const int lane = threadIdx.x & 31;
    const float* row = g_AW + ((size_t)h * S + q) * S;
    float m = -3.4e38f, z = 0.f;
    for (int k = lane; k <= q; k += 32) {
        float v = row[k];
        float nm = fmaxf(m, v);
        z = z * expf(m - nm) + expf(v - nm);
        m = nm;
    }
#pragma unroll
    for (int off = 16; off > 0; off >>= 1) {
        float om = __shfl_xor_sync(0xffffffffu, m, off);
        float oz = __shfl_xor_sync(0xffffffffu, z, off);
        float nm = fmaxf(m, om);
        z = z * expf(m - nm) + oz * expf(om - nm);
        m = nm;
    }
    if (lane == 0) { g_rowm[h * S + q] = m; g_rowz[h * S + q] = 1.f / z; }
}

__global__ void colsum_kernel() {
    const int h = blockIdx.y;
    const int k = blockIdx.x * 256 + threadIdx.x;
    const float* AWh = g_AW + (size_t)h * S * S;
    const float* rm = g_rowm + h * S;
    const float* rz = g_rowz + h * S;
    float acc = 0.f;
    for (int q = blockIdx.x * 256; q < S; q++) {
        float v = AWh[(size_t)q * S + k];
        if (q >= k) acc += expf(v - rm[q]) * rz[q];
    }
    g_scores[h * S + k] = acc;
}

// ---------------- top-k ----------------
__global__ void topk_kernel() {
    __shared__ unsigned long long key[S];
    const int h = blockIdx.x;
    const int tid = threadIdx.x;
    for (int i = tid; i < S; i += blockDim.x) {
        unsigned long long kk = 0ull;
        if (i < S - 2) {
            unsigned int b = __float_as_uint(g_scores[h * S + i]);
            b = (b & 0x80000000u) ? ~b : (b | 0x80000000u);
            kk = ((unsigned long long)b << 32) | (unsigned int)(S - 1 - i);
        }
        key[i] = kk;
    }
    __syncthreads();
    for (int ksz = 2; ksz <= S; ksz <<= 1)
        for (int j = ksz >> 1; j > 0; j >>= 1) {
            for (int i = tid; i < S; i += blockDim.x) {
                int ixj = i ^ j;
                if (ixj > i) {
                    bool up = ((i & ksz) == 0);
                    unsigned long long a = key[i], b = key[ixj];
                    if (up ? (a > b) : (a < b)) { key[i] = b; key[ixj] = a; }
                }
            }
            __syncthreads();
        }
    for (int j = tid; j < TOPK; j += blockDim.x)
        g_kidx[h * KEEP + j] = (S - 1) - (int)(key[S - 1 - j] & 0xffffffffu);
    if (tid == 0) {
        g_kidx[h * KEEP + TOPK]     = S - 2;
        g_kidx[h * KEEP + TOPK + 1] = S - 1;
    }
}

// ---------------- gather ----------------
__global__ void gather_kernel() {
    const int h = blockIdx.x;
    const int tid = threadIdx.x;
    bf16* Kkh = g_Kkh + (size_t)h * 256 * HD;
    bf16* Kkl = g_Kkl + (size_t)h * 256 * HD;
    bf16* VTh = g_VkTh + (size_t)h * HD * 256;
    bf16* VTl = g_VkTl + (size_t)h * HD * 256;
    for (int i = tid; i < 256 * HD; i += 256) {
        Kkh[i] = __float2bfloat16(0.f); Kkl[i] = __float2bfloat16(0.f);
        VTh[i] = __float2bfloat16(0.f); VTl[i] = __float2bfloat16(0.f);
    }
    __syncthreads();
    const bf16* Khh = g_Kh + (size_t)h * S * HD;
    const bf16* Khl = g_Kl + (size_t)h * S * HD;
    const float* Vh = g_V + (size_t)h * S * HD;
    for (int i = tid; i < KEEP * HD; i += 256) {
        int j = i / HD, d = i % HD;
        int kk = g_kidx[h * KEEP + j];
        Kkh[j * HD + d] = Khh[(size_t)kk * HD + d];
        Kkl[j * HD + d] = Khl[(size_t)kk * HD + d];
        split1(Vh[(size_t)kk * HD + d], VTh[d * 256 + j], VTl[d * 256 + j]);
    }
    if (tid < HD) {
        int d = tid;
        float tot = 0.f;
        for (int k = 0; k < S; k++) tot += Vh[(size_t)k * HD + d];
        float kept = 0.f;
        for (int j = 0; j < KEEP; j++)
            kept += Vh[(size_t)g_kidx[h * KEEP + j] * HD + d];
        g_negc[h * HD + d] = MV * (tot - kept);
    }
}

// ---------------- launch ----------------
extern "C" void kernel_launch(void* const* d_in, const int* in_sizes, int n_in,
                              void* d_out, int out_size)
{
    const float* hidden = (const float*)d_in[0];
    const float* Wq = (const float*)d_in[2];
    const float* Wk = (const float*)d_in[3];
    const float* Wv = (const float*)d_in[4];
    const float* Wo = (const float*)d_in[5];
    float* out = (float*)d_out;

    const int SMB = 2 * STG_B;
    cudaFuncSetAttribute(gemm_tc2<M_PROJ>,   cudaFuncAttributeMaxDynamicSharedMemorySize, SMB);
    cudaFuncSetAttribute(gemm_tc2<M_LOGITS>, cudaFuncAttributeMaxDynamicSharedMemorySize, SMB);
    cudaFuncSetAttribute(gemm_tc2<M_SP1>,    cudaFuncAttributeMaxDynamicSharedMemorySize, SMB);
    cudaFuncSetAttribute(gemm_tc2<M_SP2>,    cudaFuncAttributeMaxDynamicSharedMemorySize, SMB);
    cudaFuncSetAttribute(gemm_tc2<M_FINAL>,  cudaFuncAttributeMaxDynamicSharedMemorySize, SMB);

    const int n4H = S * HID / 4, n4W = HID * HID / 4;
    split_into_kernel<<<(n4H + 255) / 256, 256>>>(hidden, 0, n4H);
    split_into_kernel<<<(n4W + 255) / 256, 256>>>(Wq, 1, n4W);
    split_into_kernel<<<(n4W + 255) / 256, 256>>>(Wk, 2, n4W);
    split_into_kernel<<<(n4W + 255) / 256, 256>>>(Wv, 3, n4W);
    split_into_kernel<<<(n4W + 255) / 256, 256>>>(Wo, 4, n4W);

    rope_table_kernel<<<(S * 64 + 255) / 256, 256>>>();

    dim3 g_proj(3 * HID / 128, S / 128, 1);
    gemm_tc2<M_PROJ><<<g_proj, 256, SMB>>>(nullptr, HID);

    rope_apply_kernel<<<(NH * S * 64 + 255) / 256, 256>>>();

    dim3 g_log(S / 128, S / 128, NH);
    gemm_tc2<M_LOGITS><<<g_log, 256, SMB>>>(nullptr, HD);

    rowstats_kernel<<<dim3(S / 8, NH), 256>>>();
    colsum_kernel<<<dim3(S / 256, NH), 256>>>();
    topk_kernel<<<NH, 512>>>();
    gather_kernel<<<NH, 256>>>();

    dim3 g_sp1(2, S / 128, NH);
    gemm_tc2<M_SP1><<<g_sp1, 256, SMB>>>(nullptr, HD);

    dim3 g_sp2(1, S / 128, NH);
    gemm_tc2<M_SP2><<<g_sp2, 256, SMB>>>(nullptr, 256);

    dim3 g_fin(HID / 128, S / 128, 1);
    gemm_tc2<M_FINAL><<<g_fin, 256, SMB>>>(out, HID);
}